// round 15
// baseline (speedup 1.0000x reference)
#include <cuda_runtime.h>
#include <cuda_bf16.h>
#include <cuda_fp16.h>
#include <math.h>

#define CI 256
#define TOFF0 0
#define TOFF1 2097152
#define TOFF2 2621440
#define TTOT  2752512
#define AOFF0 0
#define AOFF1 24576
#define AOFF2 30720
#define ATOT  32256

__device__ float g_t [TTOT];
__device__ float g_f [TTOT];
__device__ __half2 g_w1h[256*9*128];
__device__ __half2 g_w1l[256*9*128];
__device__ __half2 g_w2h[256*9*128];
__device__ __half2 g_w2l[256*9*128];
__device__ __half2 g_xph[TTOT/2];
__device__ __half2 g_xpl[TTOT/2];
__device__ float g_wtr[256*9*16];
__device__ float g_b1[256];
__device__ float g_b2[256];
__device__ float g_score[ATOT];
__device__ float g_loc [ATOT*4];
__device__ float g_boxes[ATOT*4];
__device__ float g_sval [ATOT];
__device__ unsigned int g_keys[ATOT];
__device__ int   g_topk[6*256];
__device__ int   g_coords[2*3*32*4];
__device__ int   g_mflag [2*3*32];

__device__ __forceinline__ int lvlH(int l) { return (l==0)?64:((l==1)?32:16); }
__device__ __forceinline__ int lvlW(int l) { return (l==0)?64:((l==1)?32:16); }
__device__ __forceinline__ int lvlN(int l) { return (l==0)?12288:((l==1)?3072:768); }
__device__ __forceinline__ size_t lvlTOff(int l){ return (l==0)?TOFF0:((l==1)?(size_t)TOFF1:(size_t)TOFF2); }
__device__ __forceinline__ size_t lvlAOff(int l){ return (l==0)?AOFF0:((l==1)?(size_t)AOFF1:(size_t)AOFF2); }
__device__ __forceinline__ int lvlStride(int l){ return 8 << l; }

__device__ __forceinline__ void cp16(unsigned dst, const void* src) {
    asm volatile("cp.async.ca.shared.global [%0], [%1], 16;" :: "r"(dst), "l"(src));
}
__device__ __forceinline__ void cp16z(unsigned dst, const void* src, int ok) {
    int sz = ok ? 16 : 0;
    asm volatile("cp.async.ca.shared.global [%0], [%1], 16, %2;" :: "r"(dst), "l"(src), "r"(sz));
}
__device__ __forceinline__ void mma_f16(float* c, const unsigned* a, const unsigned* b) {
    asm volatile(
        "mma.sync.aligned.m16n8k16.row.col.f32.f16.f16.f32 "
        "{%0,%1,%2,%3}, {%4,%5,%6,%7}, {%8,%9}, {%0,%1,%2,%3};"
        : "+f"(c[0]), "+f"(c[1]), "+f"(c[2]), "+f"(c[3])
        : "r"(a[0]), "r"(a[1]), "r"(a[2]), "r"(a[3]), "r"(b[0]), "r"(b[1]));
}
#define LDSM4(r, addr) \
    asm volatile("ldmatrix.sync.aligned.m8n8.x4.shared.b16 {%0,%1,%2,%3}, [%4];" \
        : "=r"((r)[0]), "=r"((r)[1]), "=r"((r)[2]), "=r"((r)[3]) : "r"(addr))

// ---- weight transform: BN fold + f16 hi/lo, coalesced ----
// thread = (co, cipair); reads 18 consecutive floats, writes 9 coalesced taps.
__global__ void wtrans_head_k(const float* __restrict__ w, const float* __restrict__ g,
                              const float* __restrict__ bb, const float* __restrict__ mm,
                              const float* __restrict__ vv, int wsel)
{
    __half2* wph = wsel ? g_w2h : g_w1h;
    __half2* wpl = wsel ? g_w2l : g_w1l;
    float* bias = wsel ? g_b2 : g_b1;
    int i = blockIdx.x*256 + threadIdx.x;
    if (i < 256) {
        float sc = g[i] / sqrtf(vv[i] + 1e-5f);
        bias[i] = bb[i] - mm[i]*sc;
    }
    if (i >= 256*128) return;
    int co = i >> 7;
    int cp = i & 127;
    float sc = g[co] / sqrtf(vv[co] + 1e-5f);
    const float* wsrc = w + (size_t)co*2304 + cp*18;   // ci=2cp base, 18 floats
    float a[18];
#pragma unroll
    for (int t = 0; t < 18; t++) a[t] = wsrc[t] * sc;
#pragma unroll
    for (int tap = 0; tap < 9; tap++) {
        float v0 = a[tap];
        float v1 = a[9 + tap];
        __half h0 = __float2half_rn(v0);
        __half h1 = __float2half_rn(v1);
        size_t o = (size_t)co*1152 + tap*128 + cp;
        wph[o] = __halves2half2(h0, h1);
        wpl[o] = __halves2half2(__float2half_rn(v0 - __half2float(h0)),
                                __float2half_rn(v1 - __half2float(h1)));
    }
}

__global__ void wtrans_rpn_k(const float* __restrict__ clsw, const float* __restrict__ locw)
{
    int i = blockIdx.x*256 + threadIdx.x;
    if (i >= 256*9*16) return;
    int c16 = i % 16;
    int k   = (i/16) % 9;
    int ci  = i / 144;
    float v = 0.f;
    if (c16 < 3)       v = clsw[((size_t)c16*256 + ci)*9 + k];
    else if (c16 < 15) v = locw[((size_t)(c16-3)*256 + ci)*9 + k];
    g_wtr[i] = v;
}

// ---- fused FPN add + f16 hi/lo split + ci-pair pack (stage 0 inputs) ----
__global__ void split0_k(const float* __restrict__ layer2, const float* __restrict__ layer3,
                         const float* __restrict__ layer4)
{
    int gid = blockIdx.x*256 + threadIdx.x;
    if (gid >= TTOT/2) return;
    int l, hwlog, offp;
    if (gid < TOFF1/2)      { l = 0; offp = 0;        hwlog = 12; }
    else if (gid < TOFF2/2) { l = 1; offp = TOFF1/2;  hwlog = 10; }
    else                    { l = 2; offp = TOFF2/2;  hwlog = 8; }
    int HW = 1 << hwlog;
    int local = gid - offp;
    int p = local & (HW - 1);
    int plane = local >> hwlog;
    int img = plane >> 7;
    int cp = plane & 127;
    float v[2];
#pragma unroll
    for (int h = 0; h < 2; h++) {
        int bc = img*256 + 2*cp + h;
        if (l == 0) {
            int y = p >> 6, x = p & 63;
            v[h] = layer2[((size_t)bc << 12) + p]
                 + layer3[((size_t)bc << 10) + ((y>>1)<<5) + (x>>1)]
                 + layer4[((size_t)bc << 8)  + ((y>>2)<<4) + (x>>2)];
        } else if (l == 1) {
            int y = p >> 5, x = p & 31;
            v[h] = layer3[((size_t)bc << 10) + p]
                 + layer4[((size_t)bc << 8)  + ((y>>1)<<4) + (x>>1)];
        } else {
            v[h] = layer4[((size_t)bc << 8) + p];
        }
    }
    __half h0 = __float2half_rn(v[0]);
    __half h1 = __float2half_rn(v[1]);
    __half l0 = __float2half_rn(v[0] - __half2float(h0));
    __half l1 = __float2half_rn(v[1] - __half2float(h1));
    g_xph[gid] = __halves2half2(h0, h1);
    g_xpl[gid] = __halves2half2(l0, l1);
}

__global__ void split1_k()
{
    int gid = blockIdx.x*256 + threadIdx.x;
    if (gid >= TTOT/2) return;
    int l, hwlog, offp;
    if (gid < TOFF1/2)      { l = 0; offp = 0;        hwlog = 12; }
    else if (gid < TOFF2/2) { l = 1; offp = TOFF1/2;  hwlog = 10; }
    else                    { l = 2; offp = TOFF2/2;  hwlog = 8; }
    int HW = 1 << hwlog;
    int local = gid - offp;
    int p = local & (HW - 1);
    int plane = local >> hwlog;
    int img = plane >> 7;
    int cp = plane & 127;
    const float* src = g_t + lvlTOff(l);
    size_t base = ((size_t)(img*256 + 2*cp) << hwlog) + p;
    float v0 = src[base];
    float v1 = src[base + HW];
    __half h0 = __float2half_rn(v0);
    __half h1 = __float2half_rn(v1);
    __half l0 = __float2half_rn(v0 - __half2float(h0));
    __half l1 = __float2half_rn(v1 - __half2float(h1));
    g_xph[gid] = __halves2half2(h0, h1);
    g_xpl[gid] = __halves2half2(l0, l1);
}

// ---- FP16x3 implicit-GEMM conv (R11 config): row-resident B + ldmatrix A ----
#define CMM_SMEM 96256
__global__ void __launch_bounds__(256, 2) convmma_k(int stage)
{
    extern __shared__ float sm[];
    const __half2* wph = stage ? g_w2h : g_w1h;
    const __half2* wpl = stage ? g_w2l : g_w1l;
    const float* bias = stage ? g_b2 : g_b1;
    float* outbuf = stage ? g_f : g_t;

    int co0 = (blockIdx.x & 1) << 7;
    int pt = blockIdx.x >> 1;
    int l, img, ptile;
    if (pt < 128)      { l = 0; img = pt >> 6; ptile = pt & 63; }
    else if (pt < 160) { int q = pt - 128; l = 1; img = q >> 4; ptile = q & 15; }
    else               { int q = pt - 160; l = 2; img = q >> 2; ptile = q & 3; }
    int H = lvlH(l), W = lvlW(l);
    int HW = H * W;
    int logW = (l==0)?6:((l==1)?5:4);
    int R  = 64 >> logW;
    int RS = R + 2;
    int RP = W + 8;
    int CPS = (l==0)?216:((l==1)?168:152);
    int BSZ = 16*CPS;
    int Q = W >> 2;
    int logQ = logW - 2;
    int y0 = ptile * R;
    int p0 = ptile * 64;
    size_t toff = lvlTOff(l);
    const __half2* xph = g_xph + (toff>>1) + (size_t)img*128*HW;
    const __half2* xpl = g_xpl + (toff>>1) + (size_t)img*128*HW;

    int tid = threadIdx.x;
    unsigned smb = (unsigned)__cvta_generic_to_shared(sm);

    for (int t = tid; t < 64*RS; t += 256) {
        int r  = t % RS;
        int z  = t / RS;
        int cp = z & 15;
        int pr = (z >> 4) & 1;
        int bf = z >> 5;
        int base = 10240 + bf*2*BSZ + pr*BSZ + cp*CPS + r*RP;
        *(float4*)(sm + base) = make_float4(0.f,0.f,0.f,0.f);
        *(float4*)(sm + base + 4 + W) = make_float4(0.f,0.f,0.f,0.f);
    }

    auto stageB = [&](int sc) {
        unsigned bb = smb + (unsigned)((10240 + (sc & 1)*2*BSZ) * 4);
        int cq0 = sc * 16;
        int items = (RS * Q) << 4;
        for (int t = tid; t < items; t += 256) {
            int q  = t & (Q - 1);
            int rr = t >> logQ;
            int r  = rr % RS;
            int cp = rr / RS;
            int sy = y0 - 1 + r;
            int ok = (sy >= 0) && (sy < H);
            size_t src = (size_t)(cq0 + cp)*HW + (ok ? sy*W : 0) + q*4;
            unsigned d = bb + (unsigned)((cp*CPS + r*RP + 4 + q*4) * 4);
            cp16z(d, xph + src, ok);
            cp16z(d + (unsigned)(BSZ*4), xpl + src, ok);
        }
    };
    auto stageA = [&](int c) {
        int sc = c / 9;
        int tap = c - sc*9;
        unsigned ab = smb + (unsigned)((c & 1)*5120*4);
#pragma unroll
        for (int t = 0; t < 2; t++) {
            int idx = tid + (t << 8);
            int co = idx >> 2, kq = idx & 3;
            unsigned d = ab + (unsigned)((co*20 + kq*4) * 4);
            size_t go = ((size_t)(co0 + co)*9 + tap)*128 + sc*16 + kq*4;
            cp16(d,            wph + go);
            cp16(d + 2560*4,   wpl + go);
        }
    };

    stageB(0);
    stageA(0);
    asm volatile("cp.async.commit_group;" ::: "memory");
    stageA(1);
    asm volatile("cp.async.commit_group;" ::: "memory");

    int lane = tid & 31, wid = tid >> 5;
    int wm = wid & 3, wn = wid >> 2;
    int coL = wm * 32, pxL = wn * 32;
    int lr = lane >> 2, lc = lane & 3;

    unsigned aAddr[2];
#pragma unroll
    for (int m = 0; m < 2; m++)
        aAddr[m] = smb + (unsigned)((((coL + m*16 + (lane & 15))*20) + ((lane >> 4) << 2)) * 4);

    int bOff[4];
#pragma unroll
    for (int n = 0; n < 4; n++) {
        int j = pxL + n*8 + lr;
        bOff[n] = (1 + (j >> logW))*RP + 4 + (j & (W-1));
    }

    float acc[2][4][4];
#pragma unroll
    for (int m = 0; m < 2; m++)
#pragma unroll
        for (int n = 0; n < 4; n++)
#pragma unroll
            for (int q = 0; q < 4; q++) acc[m][n][q] = 0.f;

    for (int c = 0; c < 72; c++) {
        int sc = c / 9;
        int tap = c - sc*9;
        asm volatile("cp.async.wait_group 1;" ::: "memory");
        __syncthreads();
        int dyq = tap / 3;
        int tapOff = (dyq - 1)*RP + (tap - dyq*3 - 1);
        unsigned abuf = (unsigned)((c & 1)*5120*4);
        const float* Bb = sm + 10240 + (sc & 1)*2*BSZ;
#pragma unroll
        for (int st = 0; st < 2; st++) {
            int kb = st * 8;
            unsigned bh[4][2], bl[4][2];
#pragma unroll
            for (int n = 0; n < 4; n++) {
                const float* bp = Bb + (kb + lc)*CPS + bOff[n] + tapOff;
                bh[n][0] = *(const unsigned*)(bp);
                bh[n][1] = *(const unsigned*)(bp + 4*CPS);
                bl[n][0] = *(const unsigned*)(bp + BSZ);
                bl[n][1] = *(const unsigned*)(bp + 4*CPS + BSZ);
            }
#pragma unroll
            for (int m = 0; m < 2; m++) {
                unsigned ah[4], al[4];
                unsigned base = aAddr[m] + abuf + (unsigned)(kb * 4);
                LDSM4(ah, base);
                LDSM4(al, base + 2560*4);
#pragma unroll
                for (int n = 0; n < 4; n++) {
                    mma_f16(acc[m][n], ah, bh[n]);
                    mma_f16(acc[m][n], ah, bl[n]);
                    mma_f16(acc[m][n], al, bh[n]);
                }
            }
        }
        __syncthreads();
        if (c + 2 < 72) stageA(c + 2);
        if (tap == 5 && sc < 7) stageB(sc + 1);
        asm volatile("cp.async.commit_group;" ::: "memory");
    }

    float* outp = outbuf + toff + (size_t)img*256*HW;
#pragma unroll
    for (int m = 0; m < 2; m++) {
        int co = co0 + coL + m*16 + lr;
        float b0 = bias[co], b1 = bias[co + 8];
#pragma unroll
        for (int n = 0; n < 4; n++) {
            int pxo = p0 + pxL + n*8 + lc*2;
            float t0 = acc[m][n][0] + b0;
            float t1 = acc[m][n][1] + b0;
            float t2 = acc[m][n][2] + b1;
            float t3 = acc[m][n][3] + b1;
            t0 = (t0 >= 0.f) ? t0 : 0.01f*t0;
            t1 = (t1 >= 0.f) ? t1 : 0.01f*t1;
            t2 = (t2 >= 0.f) ? t2 : 0.01f*t2;
            t3 = (t3 >= 0.f) ? t3 : 0.01f*t3;
            *(float2*)(outp + (size_t)co*HW + pxo)     = make_float2(t0, t1);
            *(float2*)(outp + (size_t)(co+8)*HW + pxo) = make_float2(t2, t3);
        }
    }
}

// ---- RPN conv (FFMA, 256 threads: 32x2 px, 16 co-groups of 1) ----
#define CI_C 16
#define RISTR 40
__global__ __launch_bounds__(256, 2)
void conv_rpn_k()
{
    __shared__ float s_in[CI_C*4*RISTR];
    __shared__ float s_w [CI_C*9*16];

    int bid = blockIdx.x;
    int l, bx, by, img;
    if (bid < 128)      { l = 0; bx = bid & 1; by = (bid >> 1) & 31; img = bid >> 6; }
    else if (bid < 160) { int q = bid - 128; l = 1; bx = 0; by = q & 15; img = q >> 4; }
    else                { int q = bid - 160; l = 2; bx = 0; by = q & 7;  img = q >> 3; }
    int H = lvlH(l), W = lvlW(l);
    int HW = H * W;
    int tx = bx * 32;
    int ty = by * 2;

    int tid = threadIdx.x;
    int px  = tid & 7;
    int py  = (tid >> 3) & 1;
    int cog = tid >> 4;   // 0..15, 1 co each

    const float* inb = g_f + lvlTOff(l) + (size_t)img*256*HW;

    float acc[4];
#pragma unroll
    for (int m = 0; m < 4; m++) acc[m] = 0.f;

    for (int ci0 = 0; ci0 < CI; ci0 += CI_C) {
        if (ci0) __syncthreads();
        for (int i = tid; i < CI_C*4*34; i += 256) {
            int cc = i / 136;
            int r  = i % 136;
            int yy = r / 34;
            int xx = r % 34;
            int gy = ty + yy - 1;
            int gx = tx + xx - 1;
            float v = 0.f;
            if (gy >= 0 && gy < H && gx >= 0 && gx < W)
                v = inb[((size_t)(ci0+cc))*HW + gy*W + gx];
            s_in[(cc*4 + yy)*RISTR + xx] = v;
        }
        for (int i = tid; i < CI_C*9*16; i += 256) {
            int cc = i / 144;
            int r  = i % 144;
            s_w[i] = g_wtr[((size_t)(ci0+cc))*144 + r];
        }
        __syncthreads();

#pragma unroll 1
        for (int cc = 0; cc < CI_C; cc++) {
#pragma unroll
            for (int ky = 0; ky < 3; ky++) {
                const float* rowp = &s_in[(cc*4 + py + ky)*RISTR];
#pragma unroll
                for (int kx = 0; kx < 3; kx++) {
                    float wv = s_w[(cc*9 + ky*3 + kx)*16 + cog];
#pragma unroll
                    for (int m = 0; m < 4; m++)
                        acc[m] += rowp[px + 8*m + kx] * wv;
                }
            }
        }
    }

    int y = ty + py;
    int co = cog;
    size_t abase = lvlAOff(l) + (size_t)img*lvlN(l);
    if (co < 15) {
#pragma unroll
        for (int m = 0; m < 4; m++) {
            int x = tx + px + 8*m;
            if (x >= W) continue;
            float vv = acc[m];
            if (co < 3) {
                g_score[abase + ((size_t)y*W + x)*3 + co] = 1.f/(1.f + expf(-vv));
            } else {
                int cr = co - 3;
                g_loc[(abase + ((size_t)y*W + x)*3 + (cr>>2))*4 + (cr&3)] = vv;
            }
        }
    }
}

// ---- decode ----
__global__ void decode_k(const float* __restrict__ anch0, const float* __restrict__ anch1,
                         const float* __restrict__ anch2)
{
    int gid = blockIdx.x*256 + threadIdx.x;
    if (gid >= ATOT) return;
    int l, r;
    const float* anchors;
    if (gid < AOFF1)      { l = 0; r = gid;         anchors = anch0; }
    else if (gid < AOFF2) { l = 1; r = gid - AOFF1; anchors = anch1; }
    else                  { l = 2; r = gid - AOFF2; anchors = anch2; }
    int N = lvlN(l);
    int a = r % N;
    float stride = (float)lvlStride(l);

    float sc = g_score[gid];
    float t0 = g_loc[(size_t)gid*4 + 0];
    float t1 = g_loc[(size_t)gid*4 + 1];
    float t2 = g_loc[(size_t)gid*4 + 2];
    float t3 = g_loc[(size_t)gid*4 + 3];
    float a0 = anchors[(size_t)a*4+0], a1 = anchors[(size_t)a*4+1];
    float a2 = anchors[(size_t)a*4+2], a3 = anchors[(size_t)a*4+3];
    float aw = a2 - a0, ah = a3 - a1;
    float x1 = a0 + t0*aw;
    float y1 = a1 + t1*ah;
    float x2 = x1 + aw*expf(t2);
    float y2 = y1 + ah*expf(t3);
    x1 = fminf(fmaxf(x1, 0.f), 512.f);
    y1 = fminf(fmaxf(y1, 0.f), 512.f);
    x2 = fminf(fmaxf(x2, 0.f), 512.f);
    y2 = fminf(fmaxf(y2, 0.f), 512.f);
    bool valid = (sc > 0.5f) && ((x2 - x1) >= 2.f*stride) && ((y2 - y1) >= 2.f*stride);
    float s = valid ? sc : -1.f;
    size_t o = (size_t)gid*4;
    g_boxes[o+0] = x1; g_boxes[o+1] = y1; g_boxes[o+2] = x2; g_boxes[o+3] = y2;
    g_sval[gid] = s;
    unsigned int u = __float_as_uint(s);
    u = (u & 0x80000000u) ? ~u : (u | 0x80000000u);
    g_keys[gid] = u;
}

// ---- exact top-256 via MSB radix select ----
__global__ void topk_k()
{
    __shared__ unsigned int hist[256];
    __shared__ unsigned long long lst[256];
    __shared__ unsigned int wsum[32];
    __shared__ unsigned int sPrefix;
    __shared__ int sK, sCGT, sCnt, sTot, sDone;

    int blk = blockIdx.x;
    int l = blk >> 1;
    int b = blk & 1;
    int N = lvlN(l);
    const unsigned int* keys = g_keys + lvlAOff(l) + (size_t)b*N;
    int tid = threadIdx.x;

    if (tid == 0) { sPrefix = 0u; sK = 256; sCGT = 0; sCnt = 0; sDone = 0; }
    __syncthreads();

    for (int byte = 3; byte >= 0; byte--) {
        for (int i = tid; i < 256; i += 1024) hist[i] = 0u;
        __syncthreads();
        unsigned int pf = sPrefix;
        unsigned int mask = (byte == 3) ? 0u : (0xFFFFFFFFu << ((byte+1)*8));
        for (int i = tid; i < N; i += 1024) {
            unsigned int k = keys[i];
            if ((k & mask) == pf) atomicAdd(&hist[(k >> (byte*8)) & 255], 1u);
        }
        __syncthreads();
        if (tid == 0) {
            int cum = 0;
            int kk = sK;
            int v = 255;
            for (; v >= 0; v--) {
                int c = (int)hist[v];
                if (cum + c >= kk) break;
                cum += c;
            }
            sPrefix |= ((unsigned int)v) << (byte*8);
            sK = kk - cum;
            sCGT += cum;
        }
        __syncthreads();
    }

    unsigned int T = sPrefix;
    int need = sK;
    int cg = sCGT;

    for (int i = tid; i < N; i += 1024) {
        unsigned int k = keys[i];
        if (k > T) {
            int p = atomicAdd(&sCnt, 1);
            lst[p] = ((unsigned long long)k << 32) | (unsigned int)(0xFFFFFFFFu - i);
        }
    }
    __syncthreads();
    if (tid < 256 && tid >= cg) lst[tid] = 0ull;
    __syncthreads();

    for (int k = 2; k <= 256; k <<= 1) {
        for (int j = k >> 1; j > 0; j >>= 1) {
            if (tid < 256) {
                int ixj = tid ^ j;
                if (ixj > tid) {
                    bool desc = ((tid & k) == 0);
                    unsigned long long A = lst[tid], Bv = lst[ixj];
                    bool sw = desc ? (A < Bv) : (A > Bv);
                    if (sw) { lst[tid] = Bv; lst[ixj] = A; }
                }
            }
            __syncthreads();
        }
    }

    if (tid < cg)
        g_topk[blk*256 + tid] = (int)(0xFFFFFFFFu - (unsigned int)(lst[tid] & 0xFFFFFFFFull));

    for (int base = 0; base < N; base += 1024) {
        __syncthreads();
        if (sDone >= need) break;
        int i = base + tid;
        int flag = (i < N) && (keys[i] == T);
        unsigned int m = __ballot_sync(0xffffffffu, flag);
        int lane = tid & 31, wd = tid >> 5;
        int laneoff = __popc(m & ((1u << lane) - 1u));
        if (lane == 0) wsum[wd] = __popc(m);
        __syncthreads();
        if (tid == 0) {
            int run = 0;
            for (int w = 0; w < 32; w++) { int c = (int)wsum[w]; wsum[w] = run; run += c; }
            sTot = run;
        }
        __syncthreads();
        if (flag) {
            int pos = sDone + (int)wsum[wd] + laneoff;
            if (pos < need) g_topk[blk*256 + cg + pos] = i;
        }
        __syncthreads();
        if (tid == 0) sDone += sTot;
    }
}

// ---- greedy NMS ----
__global__ void nms_k(float* __restrict__ dout)
{
    __shared__ float bxs[256][4];
    __shared__ float varea[256];
    __shared__ float vvs[256];
    __shared__ int keep[256];
    __shared__ int ord[32];
    int blk = blockIdx.x;
    int lvl = blk >> 1;
    int b = blk & 1;
    int N = lvlN(lvl);
    int stride = lvlStride(lvl);
    size_t abase = lvlAOff(lvl) + (size_t)b*N;
    int j = threadIdx.x;
    int idx = g_topk[blk*256 + j];
    float x1 = g_boxes[(abase + idx)*4 + 0];
    float y1 = g_boxes[(abase + idx)*4 + 1];
    float x2 = g_boxes[(abase + idx)*4 + 2];
    float y2 = g_boxes[(abase + idx)*4 + 3];
    float v  = g_sval[abase + idx];
    bxs[j][0] = x1; bxs[j][1] = y1; bxs[j][2] = x2; bxs[j][3] = y2;
    vvs[j] = v;
    float areaj = (x2 - x1 + 1.f)*(y2 - y1 + 1.f);
    varea[j] = areaj;
    keep[j] = (v > 0.5f) ? 1 : 0;
    __syncthreads();
    for (int i = 0; i < 255; i++) {
        if (j > i && keep[i] && keep[j]) {
            float xx1 = fmaxf(bxs[i][0], x1);
            float yy1 = fmaxf(bxs[i][1], y1);
            float xx2 = fminf(bxs[i][2], x2);
            float yy2 = fminf(bxs[i][3], y2);
            float iw = fmaxf(0.f, xx2 - xx1 + 1.f);
            float ih = fmaxf(0.f, yy2 - yy1 + 1.f);
            float inter = iw*ih;
            float iou = inter / (varea[i] + areaj - inter);
            if (iou > 0.3f) keep[j] = 0;
        }
        __syncthreads();
    }
    if (j == 0) {
        int c = 0;
        for (int q = 0; q < 256 && c < 32; q++) if (keep[q]) ord[c++] = q;
        for (int q = 0; q < 256 && c < 32; q++) if (!keep[q]) ord[c++] = q;
    }
    __syncthreads();
    if (j < 32) {
        int o = ord[j];
        int m = keep[o];
        int slot = (b*3 + lvl)*32 + j;
        size_t dbase = (size_t)slot*5;
        if (m) {
            dout[dbase+0] = bxs[o][0];
            dout[dbase+1] = bxs[o][1];
            dout[dbase+2] = bxs[o][2];
            dout[dbase+3] = bxs[o][3];
            dout[dbase+4] = vvs[o];
        } else {
            dout[dbase+0] = 0.f; dout[dbase+1] = 0.f; dout[dbase+2] = 0.f;
            dout[dbase+3] = 0.f; dout[dbase+4] = 0.f;
        }
        dout[960 + slot] = m ? 1.f : 0.f;
        if (m) {
            g_coords[slot*4+0] = ((int)bxs[o][0]) / stride;
            g_coords[slot*4+1] = ((int)bxs[o][1]) / stride;
            g_coords[slot*4+2] = ((int)bxs[o][2]) / stride;
            g_coords[slot*4+3] = ((int)bxs[o][3]) / stride;
        } else {
            g_coords[slot*4+0] = 0; g_coords[slot*4+1] = 0;
            g_coords[slot*4+2] = 2; g_coords[slot*4+3] = 2;
        }
        g_mflag[slot] = m;
    }
}

// ---- ROI adaptive 7x7 max pool ----
__global__ void roipool_k(float* __restrict__ dout)
{
    int s = blockIdx.x;
    int b = blockIdx.y;
    int lvl = blockIdx.z;
    int c = threadIdx.x;
    int H = lvlH(lvl), W = lvlW(lvl);
    int slot = (b*3 + lvl)*32 + s;
    float* dst = dout + 1152 + ((size_t)slot*256 + c)*49;
    int m = g_mflag[slot];
    if (!m) {
#pragma unroll
        for (int k = 0; k < 49; k++) dst[k] = 0.f;
        return;
    }
    int x1 = g_coords[slot*4+0];
    int y1 = g_coords[slot*4+1];
    int x2 = g_coords[slot*4+2];
    int y2 = g_coords[slot*4+3];
    int Lx = x2 - x1;
    int Ly = y2 - y1;
    const float* f = g_f + lvlTOff(lvl) + ((size_t)b*256 + c)*H*W;
    for (int i = 0; i < 7; i++) {
        int ys = y1 + (i*Ly)/7;
        int ye = y1 + ((i+1)*Ly + 6)/7;
        for (int jx = 0; jx < 7; jx++) {
            int xs = x1 + (jx*Lx)/7;
            int xe = x1 + ((jx+1)*Lx + 6)/7;
            float mx = -3.402823466e38f;
            for (int y = ys; y < ye; y++)
                for (int x = xs; x < xe; x++)
                    mx = fmaxf(mx, f[y*W + x]);
            dst[i*7 + jx] = mx;
        }
    }
}

// ---- host orchestration (kernel launches ONLY) ----
extern "C" void kernel_launch(void* const* d_in, const int* in_sizes, int n_in,
                              void* d_out, int out_size)
{
    const float* layer2   = (const float*)d_in[0];
    const float* layer3   = (const float*)d_in[1];
    const float* layer4   = (const float*)d_in[2];
    const float* anchors2 = (const float*)d_in[3];
    const float* anchors3 = (const float*)d_in[4];
    const float* anchors4 = (const float*)d_in[5];
    const float* hw1 = (const float*)d_in[6];
    const float* hg1 = (const float*)d_in[7];
    const float* hb1 = (const float*)d_in[8];
    const float* hm1 = (const float*)d_in[9];
    const float* hv1 = (const float*)d_in[10];
    const float* hw2 = (const float*)d_in[11];
    const float* hg2 = (const float*)d_in[12];
    const float* hb2 = (const float*)d_in[13];
    const float* hm2 = (const float*)d_in[14];
    const float* hv2 = (const float*)d_in[15];
    const float* clsw = (const float*)d_in[16];
    const float* locw = (const float*)d_in[17];
    float* out = (float*)d_out;

    cudaFuncSetAttribute(convmma_k, cudaFuncAttributeMaxDynamicSharedMemorySize,
                         CMM_SMEM);

    wtrans_head_k<<<128, 256>>>(hw1, hg1, hb1, hm1, hv1, 0);
    wtrans_head_k<<<128, 256>>>(hw2, hg2, hb2, hm2, hv2, 1);
    split0_k<<<(TTOT/2 + 255)/256, 256>>>(layer2, layer3, layer4);
    convmma_k<<<336, 256, CMM_SMEM>>>(0);
    split1_k<<<(TTOT/2 + 255)/256, 256>>>();
    convmma_k<<<336, 256, CMM_SMEM>>>(1);

    wtrans_rpn_k<<<(256*9*16 + 255)/256, 256>>>(clsw, locw);
    conv_rpn_k<<<176, 256>>>();

    decode_k<<<(ATOT + 255)/256, 256>>>(anchors2, anchors3, anchors4);
    topk_k<<<6, 1024>>>();
    nms_k<<<6, 256>>>(out);
    roipool_k<<<dim3(32, 2, 3), 256>>>(out);
}

// round 16
// speedup vs baseline: 1.0385x; 1.0385x over previous
#include <cuda_runtime.h>
#include <cuda_bf16.h>
#include <cuda_fp16.h>
#include <math.h>

#define CI 256
#define TOFF0 0
#define TOFF1 2097152
#define TOFF2 2621440
#define TTOT  2752512
#define AOFF0 0
#define AOFF1 24576
#define AOFF2 30720
#define ATOT  32256

__device__ float g_t [TTOT];
__device__ float g_f [TTOT];
__device__ __half2 g_w1h[256*9*128];
__device__ __half2 g_w1l[256*9*128];
__device__ __half2 g_w2h[256*9*128];
__device__ __half2 g_w2l[256*9*128];
__device__ __half2 g_xph[TTOT/2];
__device__ __half2 g_xpl[TTOT/2];
__device__ float g_wtr[256*9*16];
__device__ float g_b1[256];
__device__ float g_b2[256];
__device__ float g_score[ATOT];
__device__ float g_loc [ATOT*4];
__device__ float g_boxes[ATOT*4];
__device__ float g_sval [ATOT];
__device__ unsigned int g_keys[ATOT];
__device__ int   g_topk[6*256];
__device__ int   g_coords[2*3*32*4];
__device__ int   g_mflag [2*3*32];

__device__ __forceinline__ int lvlH(int l) { return (l==0)?64:((l==1)?32:16); }
__device__ __forceinline__ int lvlW(int l) { return (l==0)?64:((l==1)?32:16); }
__device__ __forceinline__ int lvlN(int l) { return (l==0)?12288:((l==1)?3072:768); }
__device__ __forceinline__ size_t lvlTOff(int l){ return (l==0)?TOFF0:((l==1)?(size_t)TOFF1:(size_t)TOFF2); }
__device__ __forceinline__ size_t lvlAOff(int l){ return (l==0)?AOFF0:((l==1)?(size_t)AOFF1:(size_t)AOFF2); }
__device__ __forceinline__ int lvlStride(int l){ return 8 << l; }

__device__ __forceinline__ void cp16(unsigned dst, const void* src) {
    asm volatile("cp.async.ca.shared.global [%0], [%1], 16;" :: "r"(dst), "l"(src));
}
__device__ __forceinline__ void cp16z(unsigned dst, const void* src, int ok) {
    int sz = ok ? 16 : 0;
    asm volatile("cp.async.ca.shared.global [%0], [%1], 16, %2;" :: "r"(dst), "l"(src), "r"(sz));
}
__device__ __forceinline__ void mma_f16(float* c, const unsigned* a, const unsigned* b) {
    asm volatile(
        "mma.sync.aligned.m16n8k16.row.col.f32.f16.f16.f32 "
        "{%0,%1,%2,%3}, {%4,%5,%6,%7}, {%8,%9}, {%0,%1,%2,%3};"
        : "+f"(c[0]), "+f"(c[1]), "+f"(c[2]), "+f"(c[3])
        : "r"(a[0]), "r"(a[1]), "r"(a[2]), "r"(a[3]), "r"(b[0]), "r"(b[1]));
}
#define LDSM4(r, addr) \
    asm volatile("ldmatrix.sync.aligned.m8n8.x4.shared.b16 {%0,%1,%2,%3}, [%4];" \
        : "=r"((r)[0]), "=r"((r)[1]), "=r"((r)[2]), "=r"((r)[3]) : "r"(addr))

// ---- weight transform: BN fold + f16 hi/lo, [co][tap][128 cipair] ----
__global__ void wtrans_head_k(const float* __restrict__ w, const float* __restrict__ g,
                              const float* __restrict__ bb, const float* __restrict__ mm,
                              const float* __restrict__ vv, int wsel)
{
    __half2* wph = wsel ? g_w2h : g_w1h;
    __half2* wpl = wsel ? g_w2l : g_w1l;
    float* bias = wsel ? g_b2 : g_b1;
    int i = blockIdx.x*256 + threadIdx.x;
    if (i < 256) {
        float sc = g[i] / sqrtf(vv[i] + 1e-5f);
        bias[i] = bb[i] - mm[i]*sc;
    }
    if (i >= 256*9*128) return;
    int cp  = i % 128;
    int tap = (i/128) % 9;
    int co  = i / 1152;
    float sc = g[co] / sqrtf(vv[co] + 1e-5f);
    float v0 = w[((size_t)co*256 + 2*cp)*9 + tap] * sc;
    float v1 = w[((size_t)co*256 + 2*cp + 1)*9 + tap] * sc;
    __half h0 = __float2half_rn(v0);
    __half h1 = __float2half_rn(v1);
    __half l0 = __float2half_rn(v0 - __half2float(h0));
    __half l1 = __float2half_rn(v1 - __half2float(h1));
    wph[i] = __halves2half2(h0, h1);
    wpl[i] = __halves2half2(l0, l1);
}

__global__ void wtrans_rpn_k(const float* __restrict__ clsw, const float* __restrict__ locw)
{
    int i = blockIdx.x*256 + threadIdx.x;
    if (i >= 256*9*16) return;
    int c16 = i % 16;
    int k   = (i/16) % 9;
    int ci  = i / 144;
    float v = 0.f;
    if (c16 < 3)       v = clsw[((size_t)c16*256 + ci)*9 + k];
    else if (c16 < 15) v = locw[((size_t)(c16-3)*256 + ci)*9 + k];
    g_wtr[i] = v;
}

// ---- fused FPN add + f16 hi/lo split + ci-pair pack (stage 0 inputs) ----
__global__ void split0_k(const float* __restrict__ layer2, const float* __restrict__ layer3,
                         const float* __restrict__ layer4)
{
    int gid = blockIdx.x*256 + threadIdx.x;
    if (gid >= TTOT/2) return;
    int l, hwlog, offp;
    if (gid < TOFF1/2)      { l = 0; offp = 0;        hwlog = 12; }
    else if (gid < TOFF2/2) { l = 1; offp = TOFF1/2;  hwlog = 10; }
    else                    { l = 2; offp = TOFF2/2;  hwlog = 8; }
    int HW = 1 << hwlog;
    int local = gid - offp;
    int p = local & (HW - 1);
    int plane = local >> hwlog;
    int img = plane >> 7;
    int cp = plane & 127;
    float v[2];
#pragma unroll
    for (int h = 0; h < 2; h++) {
        int bc = img*256 + 2*cp + h;
        if (l == 0) {
            int y = p >> 6, x = p & 63;
            v[h] = layer2[((size_t)bc << 12) + p]
                 + layer3[((size_t)bc << 10) + ((y>>1)<<5) + (x>>1)]
                 + layer4[((size_t)bc << 8)  + ((y>>2)<<4) + (x>>2)];
        } else if (l == 1) {
            int y = p >> 5, x = p & 31;
            v[h] = layer3[((size_t)bc << 10) + p]
                 + layer4[((size_t)bc << 8)  + ((y>>1)<<4) + (x>>1)];
        } else {
            v[h] = layer4[((size_t)bc << 8) + p];
        }
    }
    __half h0 = __float2half_rn(v[0]);
    __half h1 = __float2half_rn(v[1]);
    __half l0 = __float2half_rn(v[0] - __half2float(h0));
    __half l1 = __float2half_rn(v[1] - __half2float(h1));
    g_xph[gid] = __halves2half2(h0, h1);
    g_xpl[gid] = __halves2half2(l0, l1);
}

__global__ void split1_k()
{
    int gid = blockIdx.x*256 + threadIdx.x;
    if (gid >= TTOT/2) return;
    int l, hwlog, offp;
    if (gid < TOFF1/2)      { l = 0; offp = 0;        hwlog = 12; }
    else if (gid < TOFF2/2) { l = 1; offp = TOFF1/2;  hwlog = 10; }
    else                    { l = 2; offp = TOFF2/2;  hwlog = 8; }
    int HW = 1 << hwlog;
    int local = gid - offp;
    int p = local & (HW - 1);
    int plane = local >> hwlog;
    int img = plane >> 7;
    int cp = plane & 127;
    const float* src = g_t + lvlTOff(l);
    size_t base = ((size_t)(img*256 + 2*cp) << hwlog) + p;
    float v0 = src[base];
    float v1 = src[base + HW];
    __half h0 = __float2half_rn(v0);
    __half h1 = __float2half_rn(v1);
    __half l0 = __float2half_rn(v0 - __half2float(h0));
    __half l1 = __float2half_rn(v1 - __half2float(h1));
    g_xph[gid] = __halves2half2(h0, h1);
    g_xpl[gid] = __halves2half2(l0, l1);
}

// ---- FP16x3 implicit-GEMM conv (R11 config + term-major mma ordering) ----
// Block 128co x 64px, 336 blocks, occ 2. Chunk c = sc*9 + tap.
// mma issued term-major: 8 indep Ah*Bh, 8 indep Ah*Bl, 8 indep Al*Bh —
// per-accumulator order unchanged (hh, hl, lh) => bit-identical results.
#define CMM_SMEM 96256
__global__ void __launch_bounds__(256, 2) convmma_k(int stage)
{
    extern __shared__ float sm[];
    const __half2* wph = stage ? g_w2h : g_w1h;
    const __half2* wpl = stage ? g_w2l : g_w1l;
    const float* bias = stage ? g_b2 : g_b1;
    float* outbuf = stage ? g_f : g_t;

    int co0 = (blockIdx.x & 1) << 7;
    int pt = blockIdx.x >> 1;
    int l, img, ptile;
    if (pt < 128)      { l = 0; img = pt >> 6; ptile = pt & 63; }
    else if (pt < 160) { int q = pt - 128; l = 1; img = q >> 4; ptile = q & 15; }
    else               { int q = pt - 160; l = 2; img = q >> 2; ptile = q & 3; }
    int H = lvlH(l), W = lvlW(l);
    int HW = H * W;
    int logW = (l==0)?6:((l==1)?5:4);
    int R  = 64 >> logW;
    int RS = R + 2;
    int RP = W + 8;
    int CPS = (l==0)?216:((l==1)?168:152);
    int BSZ = 16*CPS;
    int Q = W >> 2;
    int logQ = logW - 2;
    int y0 = ptile * R;
    int p0 = ptile * 64;
    size_t toff = lvlTOff(l);
    const __half2* xph = g_xph + (toff>>1) + (size_t)img*128*HW;
    const __half2* xpl = g_xpl + (toff>>1) + (size_t)img*128*HW;

    int tid = threadIdx.x;
    unsigned smb = (unsigned)__cvta_generic_to_shared(sm);

    for (int t = tid; t < 64*RS; t += 256) {
        int r  = t % RS;
        int z  = t / RS;
        int cp = z & 15;
        int pr = (z >> 4) & 1;
        int bf = z >> 5;
        int base = 10240 + bf*2*BSZ + pr*BSZ + cp*CPS + r*RP;
        *(float4*)(sm + base) = make_float4(0.f,0.f,0.f,0.f);
        *(float4*)(sm + base + 4 + W) = make_float4(0.f,0.f,0.f,0.f);
    }

    auto stageB = [&](int sc) {
        unsigned bb = smb + (unsigned)((10240 + (sc & 1)*2*BSZ) * 4);
        int cq0 = sc * 16;
        int items = (RS * Q) << 4;
        for (int t = tid; t < items; t += 256) {
            int q  = t & (Q - 1);
            int rr = t >> logQ;
            int r  = rr % RS;
            int cp = rr / RS;
            int sy = y0 - 1 + r;
            int ok = (sy >= 0) && (sy < H);
            size_t src = (size_t)(cq0 + cp)*HW + (ok ? sy*W : 0) + q*4;
            unsigned d = bb + (unsigned)((cp*CPS + r*RP + 4 + q*4) * 4);
            cp16z(d, xph + src, ok);
            cp16z(d + (unsigned)(BSZ*4), xpl + src, ok);
        }
    };
    auto stageA = [&](int c) {
        int sc = c / 9;
        int tap = c - sc*9;
        unsigned ab = smb + (unsigned)((c & 1)*5120*4);
#pragma unroll
        for (int t = 0; t < 2; t++) {
            int idx = tid + (t << 8);
            int co = idx >> 2, kq = idx & 3;
            unsigned d = ab + (unsigned)((co*20 + kq*4) * 4);
            size_t go = ((size_t)(co0 + co)*9 + tap)*128 + sc*16 + kq*4;
            cp16(d,            wph + go);
            cp16(d + 2560*4,   wpl + go);
        }
    };

    stageB(0);
    stageA(0);
    asm volatile("cp.async.commit_group;" ::: "memory");
    stageA(1);
    asm volatile("cp.async.commit_group;" ::: "memory");

    int lane = tid & 31, wid = tid >> 5;
    int wm = wid & 3, wn = wid >> 2;
    int coL = wm * 32, pxL = wn * 32;
    int lr = lane >> 2, lc = lane & 3;

    unsigned aAddr[2];
#pragma unroll
    for (int m = 0; m < 2; m++)
        aAddr[m] = smb + (unsigned)((((coL + m*16 + (lane & 15))*20) + ((lane >> 4) << 2)) * 4);

    int bOff[4];
#pragma unroll
    for (int n = 0; n < 4; n++) {
        int j = pxL + n*8 + lr;
        bOff[n] = (1 + (j >> logW))*RP + 4 + (j & (W-1));
    }

    float acc[2][4][4];
#pragma unroll
    for (int m = 0; m < 2; m++)
#pragma unroll
        for (int n = 0; n < 4; n++)
#pragma unroll
            for (int q = 0; q < 4; q++) acc[m][n][q] = 0.f;

    for (int c = 0; c < 72; c++) {
        int sc = c / 9;
        int tap = c - sc*9;
        asm volatile("cp.async.wait_group 1;" ::: "memory");
        __syncthreads();
        int dyq = tap / 3;
        int tapOff = (dyq - 1)*RP + (tap - dyq*3 - 1);
        unsigned abuf = (unsigned)((c & 1)*5120*4);
        const float* Bb = sm + 10240 + (sc & 1)*2*BSZ;
#pragma unroll
        for (int st = 0; st < 2; st++) {
            int kb = st * 8;
            unsigned bh[4][2], bl[4][2];
#pragma unroll
            for (int n = 0; n < 4; n++) {
                const float* bp = Bb + (kb + lc)*CPS + bOff[n] + tapOff;
                bh[n][0] = *(const unsigned*)(bp);
                bh[n][1] = *(const unsigned*)(bp + 4*CPS);
                bl[n][0] = *(const unsigned*)(bp + BSZ);
                bl[n][1] = *(const unsigned*)(bp + 4*CPS + BSZ);
            }
            unsigned ah[2][4], al[2][4];
#pragma unroll
            for (int m = 0; m < 2; m++) {
                unsigned base = aAddr[m] + abuf + (unsigned)(kb * 4);
                LDSM4(ah[m], base);
                LDSM4(al[m], base + 2560*4);
            }
            // term-major passes: 8 independent mmas each; per-acc order hh,hl,lh
#pragma unroll
            for (int m = 0; m < 2; m++)
#pragma unroll
                for (int n = 0; n < 4; n++)
                    mma_f16(acc[m][n], ah[m], bh[n]);
#pragma unroll
            for (int m = 0; m < 2; m++)
#pragma unroll
                for (int n = 0; n < 4; n++)
                    mma_f16(acc[m][n], ah[m], bl[n]);
#pragma unroll
            for (int m = 0; m < 2; m++)
#pragma unroll
                for (int n = 0; n < 4; n++)
                    mma_f16(acc[m][n], al[m], bh[n]);
        }
        __syncthreads();
        if (c + 2 < 72) stageA(c + 2);
        if (tap == 5 && sc < 7) stageB(sc + 1);
        asm volatile("cp.async.commit_group;" ::: "memory");
    }

    float* outp = outbuf + toff + (size_t)img*256*HW;
#pragma unroll
    for (int m = 0; m < 2; m++) {
        int co = co0 + coL + m*16 + lr;
        float b0 = bias[co], b1 = bias[co + 8];
#pragma unroll
        for (int n = 0; n < 4; n++) {
            int pxo = p0 + pxL + n*8 + lc*2;
            float t0 = acc[m][n][0] + b0;
            float t1 = acc[m][n][1] + b0;
            float t2 = acc[m][n][2] + b1;
            float t3 = acc[m][n][3] + b1;
            t0 = (t0 >= 0.f) ? t0 : 0.01f*t0;
            t1 = (t1 >= 0.f) ? t1 : 0.01f*t1;
            t2 = (t2 >= 0.f) ? t2 : 0.01f*t2;
            t3 = (t3 >= 0.f) ? t3 : 0.01f*t3;
            *(float2*)(outp + (size_t)co*HW + pxo)     = make_float2(t0, t1);
            *(float2*)(outp + (size_t)(co+8)*HW + pxo) = make_float2(t2, t3);
        }
    }
}

// ---- RPN conv (FFMA, 32x2 px, 16 co, 176 blocks) ----
#define CI_C 16
#define RISTR 40
__global__ __launch_bounds__(128, 4)
void conv_rpn_k()
{
    __shared__ float s_in[CI_C*4*RISTR];
    __shared__ float s_w [CI_C*9*16];

    int bid = blockIdx.x;
    int l, bx, by, img;
    if (bid < 128)      { l = 0; bx = bid & 1; by = (bid >> 1) & 31; img = bid >> 6; }
    else if (bid < 160) { int q = bid - 128; l = 1; bx = 0; by = q & 15; img = q >> 4; }
    else                { int q = bid - 160; l = 2; bx = 0; by = q & 7;  img = q >> 3; }
    int H = lvlH(l), W = lvlW(l);
    int HW = H * W;
    int tx = bx * 32;
    int ty = by * 2;

    int tid = threadIdx.x;
    int px  = tid & 7;
    int py  = (tid >> 3) & 1;
    int cog = tid >> 4;

    const float* inb = g_f + lvlTOff(l) + (size_t)img*256*HW;

    float acc[2][4];
#pragma unroll
    for (int a = 0; a < 2; a++)
#pragma unroll
        for (int m = 0; m < 4; m++) acc[a][m] = 0.f;

    for (int ci0 = 0; ci0 < CI; ci0 += CI_C) {
        if (ci0) __syncthreads();
        for (int i = tid; i < CI_C*4*34; i += 128) {
            int cc = i / 136;
            int r  = i % 136;
            int yy = r / 34;
            int xx = r % 34;
            int gy = ty + yy - 1;
            int gx = tx + xx - 1;
            float v = 0.f;
            if (gy >= 0 && gy < H && gx >= 0 && gx < W)
                v = inb[((size_t)(ci0+cc))*HW + gy*W + gx];
            s_in[(cc*4 + yy)*RISTR + xx] = v;
        }
        for (int i = tid; i < CI_C*9*16; i += 128) {
            int cc = i / 144;
            int r  = i % 144;
            s_w[i] = g_wtr[((size_t)(ci0+cc))*144 + r];
        }
        __syncthreads();

#pragma unroll 1
        for (int cc = 0; cc < CI_C; cc++) {
#pragma unroll
            for (int ky = 0; ky < 3; ky++) {
                const float* rowp = &s_in[(cc*4 + py + ky)*RISTR];
#pragma unroll
                for (int kx = 0; kx < 3; kx++) {
                    float2 w2 = *(const float2*)&s_w[(cc*9 + ky*3 + kx)*16 + cog*2];
#pragma unroll
                    for (int m = 0; m < 4; m++) {
                        float v = rowp[px + 8*m + kx];
                        acc[0][m] += v * w2.x;
                        acc[1][m] += v * w2.y;
                    }
                }
            }
        }
    }

    int y = ty + py;
    size_t abase = lvlAOff(l) + (size_t)img*lvlN(l);
#pragma unroll
    for (int m = 0; m < 4; m++) {
        int x = tx + px + 8*m;
        if (x >= W) continue;
#pragma unroll
        for (int a = 0; a < 2; a++) {
            int co = cog*2 + a;
            if (co >= 15) break;
            float vv = acc[a][m];
            if (co < 3) {
                g_score[abase + ((size_t)y*W + x)*3 + co] = 1.f/(1.f + expf(-vv));
            } else {
                int cr = co - 3;
                g_loc[(abase + ((size_t)y*W + x)*3 + (cr>>2))*4 + (cr&3)] = vv;
            }
        }
    }
}

// ---- decode ----
__global__ void decode_k(const float* __restrict__ anch0, const float* __restrict__ anch1,
                         const float* __restrict__ anch2)
{
    int gid = blockIdx.x*256 + threadIdx.x;
    if (gid >= ATOT) return;
    int l, r;
    const float* anchors;
    if (gid < AOFF1)      { l = 0; r = gid;         anchors = anch0; }
    else if (gid < AOFF2) { l = 1; r = gid - AOFF1; anchors = anch1; }
    else                  { l = 2; r = gid - AOFF2; anchors = anch2; }
    int N = lvlN(l);
    int a = r % N;
    float stride = (float)lvlStride(l);

    float sc = g_score[gid];
    float t0 = g_loc[(size_t)gid*4 + 0];
    float t1 = g_loc[(size_t)gid*4 + 1];
    float t2 = g_loc[(size_t)gid*4 + 2];
    float t3 = g_loc[(size_t)gid*4 + 3];
    float a0 = anchors[(size_t)a*4+0], a1 = anchors[(size_t)a*4+1];
    float a2 = anchors[(size_t)a*4+2], a3 = anchors[(size_t)a*4+3];
    float aw = a2 - a0, ah = a3 - a1;
    float x1 = a0 + t0*aw;
    float y1 = a1 + t1*ah;
    float x2 = x1 + aw*expf(t2);
    float y2 = y1 + ah*expf(t3);
    x1 = fminf(fmaxf(x1, 0.f), 512.f);
    y1 = fminf(fmaxf(y1, 0.f), 512.f);
    x2 = fminf(fmaxf(x2, 0.f), 512.f);
    y2 = fminf(fmaxf(y2, 0.f), 512.f);
    bool valid = (sc > 0.5f) && ((x2 - x1) >= 2.f*stride) && ((y2 - y1) >= 2.f*stride);
    float s = valid ? sc : -1.f;
    size_t o = (size_t)gid*4;
    g_boxes[o+0] = x1; g_boxes[o+1] = y1; g_boxes[o+2] = x2; g_boxes[o+3] = y2;
    g_sval[gid] = s;
    unsigned int u = __float_as_uint(s);
    u = (u & 0x80000000u) ? ~u : (u | 0x80000000u);
    g_keys[gid] = u;
}

// ---- exact top-256 via MSB radix select ----
__global__ void topk_k()
{
    __shared__ unsigned int hist[256];
    __shared__ unsigned long long lst[256];
    __shared__ unsigned int wsum[32];
    __shared__ unsigned int sPrefix;
    __shared__ int sK, sCGT, sCnt, sTot, sDone;

    int blk = blockIdx.x;
    int l = blk >> 1;
    int b = blk & 1;
    int N = lvlN(l);
    const unsigned int* keys = g_keys + lvlAOff(l) + (size_t)b*N;
    int tid = threadIdx.x;

    if (tid == 0) { sPrefix = 0u; sK = 256; sCGT = 0; sCnt = 0; sDone = 0; }
    __syncthreads();

    for (int byte = 3; byte >= 0; byte--) {
        for (int i = tid; i < 256; i += 1024) hist[i] = 0u;
        __syncthreads();
        unsigned int pf = sPrefix;
        unsigned int mask = (byte == 3) ? 0u : (0xFFFFFFFFu << ((byte+1)*8));
        for (int i = tid; i < N; i += 1024) {
            unsigned int k = keys[i];
            if ((k & mask) == pf) atomicAdd(&hist[(k >> (byte*8)) & 255], 1u);
        }
        __syncthreads();
        if (tid == 0) {
            int cum = 0;
            int kk = sK;
            int v = 255;
            for (; v >= 0; v--) {
                int c = (int)hist[v];
                if (cum + c >= kk) break;
                cum += c;
            }
            sPrefix |= ((unsigned int)v) << (byte*8);
            sK = kk - cum;
            sCGT += cum;
        }
        __syncthreads();
    }

    unsigned int T = sPrefix;
    int need = sK;
    int cg = sCGT;

    for (int i = tid; i < N; i += 1024) {
        unsigned int k = keys[i];
        if (k > T) {
            int p = atomicAdd(&sCnt, 1);
            lst[p] = ((unsigned long long)k << 32) | (unsigned int)(0xFFFFFFFFu - i);
        }
    }
    __syncthreads();
    if (tid < 256 && tid >= cg) lst[tid] = 0ull;
    __syncthreads();

    for (int k = 2; k <= 256; k <<= 1) {
        for (int j = k >> 1; j > 0; j >>= 1) {
            if (tid < 256) {
                int ixj = tid ^ j;
                if (ixj > tid) {
                    bool desc = ((tid & k) == 0);
                    unsigned long long A = lst[tid], Bv = lst[ixj];
                    bool sw = desc ? (A < Bv) : (A > Bv);
                    if (sw) { lst[tid] = Bv; lst[ixj] = A; }
                }
            }
            __syncthreads();
        }
    }

    if (tid < cg)
        g_topk[blk*256 + tid] = (int)(0xFFFFFFFFu - (unsigned int)(lst[tid] & 0xFFFFFFFFull));

    for (int base = 0; base < N; base += 1024) {
        __syncthreads();
        if (sDone >= need) break;
        int i = base + tid;
        int flag = (i < N) && (keys[i] == T);
        unsigned int m = __ballot_sync(0xffffffffu, flag);
        int lane = tid & 31, wd = tid >> 5;
        int laneoff = __popc(m & ((1u << lane) - 1u));
        if (lane == 0) wsum[wd] = __popc(m);
        __syncthreads();
        if (tid == 0) {
            int run = 0;
            for (int w = 0; w < 32; w++) { int c = (int)wsum[w]; wsum[w] = run; run += c; }
            sTot = run;
        }
        __syncthreads();
        if (flag) {
            int pos = sDone + (int)wsum[wd] + laneoff;
            if (pos < need) g_topk[blk*256 + cg + pos] = i;
        }
        __syncthreads();
        if (tid == 0) sDone += sTot;
    }
}

// ---- greedy NMS ----
__global__ void nms_k(float* __restrict__ dout)
{
    __shared__ float bxs[256][4];
    __shared__ float varea[256];
    __shared__ float vvs[256];
    __shared__ int keep[256];
    __shared__ int ord[32];
    int blk = blockIdx.x;
    int lvl = blk >> 1;
    int b = blk & 1;
    int N = lvlN(lvl);
    int stride = lvlStride(lvl);
    size_t abase = lvlAOff(lvl) + (size_t)b*N;
    int j = threadIdx.x;
    int idx = g_topk[blk*256 + j];
    float x1 = g_boxes[(abase + idx)*4 + 0];
    float y1 = g_boxes[(abase + idx)*4 + 1];
    float x2 = g_boxes[(abase + idx)*4 + 2];
    float y2 = g_boxes[(abase + idx)*4 + 3];
    float v  = g_sval[abase + idx];
    bxs[j][0] = x1; bxs[j][1] = y1; bxs[j][2] = x2; bxs[j][3] = y2;
    vvs[j] = v;
    float areaj = (x2 - x1 + 1.f)*(y2 - y1 + 1.f);
    varea[j] = areaj;
    keep[j] = (v > 0.5f) ? 1 : 0;
    __syncthreads();
    for (int i = 0; i < 255; i++) {
        if (j > i && keep[i] && keep[j]) {
            float xx1 = fmaxf(bxs[i][0], x1);
            float yy1 = fmaxf(bxs[i][1], y1);
            float xx2 = fminf(bxs[i][2], x2);
            float yy2 = fminf(bxs[i][3], y2);
            float iw = fmaxf(0.f, xx2 - xx1 + 1.f);
            float ih = fmaxf(0.f, yy2 - yy1 + 1.f);
            float inter = iw*ih;
            float iou = inter / (varea[i] + areaj - inter);
            if (iou > 0.3f) keep[j] = 0;
        }
        __syncthreads();
    }
    if (j == 0) {
        int c = 0;
        for (int q = 0; q < 256 && c < 32; q++) if (keep[q]) ord[c++] = q;
        for (int q = 0; q < 256 && c < 32; q++) if (!keep[q]) ord[c++] = q;
    }
    __syncthreads();
    if (j < 32) {
        int o = ord[j];
        int m = keep[o];
        int slot = (b*3 + lvl)*32 + j;
        size_t dbase = (size_t)slot*5;
        if (m) {
            dout[dbase+0] = bxs[o][0];
            dout[dbase+1] = bxs[o][1];
            dout[dbase+2] = bxs[o][2];
            dout[dbase+3] = bxs[o][3];
            dout[dbase+4] = vvs[o];
        } else {
            dout[dbase+0] = 0.f; dout[dbase+1] = 0.f; dout[dbase+2] = 0.f;
            dout[dbase+3] = 0.f; dout[dbase+4] = 0.f;
        }
        dout[960 + slot] = m ? 1.f : 0.f;
        if (m) {
            g_coords[slot*4+0] = ((int)bxs[o][0]) / stride;
            g_coords[slot*4+1] = ((int)bxs[o][1]) / stride;
            g_coords[slot*4+2] = ((int)bxs[o][2]) / stride;
            g_coords[slot*4+3] = ((int)bxs[o][3]) / stride;
        } else {
            g_coords[slot*4+0] = 0; g_coords[slot*4+1] = 0;
            g_coords[slot*4+2] = 2; g_coords[slot*4+3] = 2;
        }
        g_mflag[slot] = m;
    }
}

// ---- ROI adaptive 7x7 max pool ----
__global__ void roipool_k(float* __restrict__ dout)
{
    int s = blockIdx.x;
    int b = blockIdx.y;
    int lvl = blockIdx.z;
    int c = threadIdx.x;
    int H = lvlH(lvl), W = lvlW(lvl);
    int slot = (b*3 + lvl)*32 + s;
    float* dst = dout + 1152 + ((size_t)slot*256 + c)*49;
    int m = g_mflag[slot];
    if (!m) {
#pragma unroll
        for (int k = 0; k < 49; k++) dst[k] = 0.f;
        return;
    }
    int x1 = g_coords[slot*4+0];
    int y1 = g_coords[slot*4+1];
    int x2 = g_coords[slot*4+2];
    int y2 = g_coords[slot*4+3];
    int Lx = x2 - x1;
    int Ly = y2 - y1;
    const float* f = g_f + lvlTOff(lvl) + ((size_t)b*256 + c)*H*W;
    for (int i = 0; i < 7; i++) {
        int ys = y1 + (i*Ly)/7;
        int ye = y1 + ((i+1)*Ly + 6)/7;
        for (int jx = 0; jx < 7; jx++) {
            int xs = x1 + (jx*Lx)/7;
            int xe = x1 + ((jx+1)*Lx + 6)/7;
            float mx = -3.402823466e38f;
            for (int y = ys; y < ye; y++)
                for (int x = xs; x < xe; x++)
                    mx = fmaxf(mx, f[y*W + x]);
            dst[i*7 + jx] = mx;
        }
    }
}

// ---- host orchestration (kernel launches ONLY) ----
extern "C" void kernel_launch(void* const* d_in, const int* in_sizes, int n_in,
                              void* d_out, int out_size)
{
    const float* layer2   = (const float*)d_in[0];
    const float* layer3   = (const float*)d_in[1];
    const float* layer4   = (const float*)d_in[2];
    const float* anchors2 = (const float*)d_in[3];
    const float* anchors3 = (const float*)d_in[4];
    const float* anchors4 = (const float*)d_in[5];
    const float* hw1 = (const float*)d_in[6];
    const float* hg1 = (const float*)d_in[7];
    const float* hb1 = (const float*)d_in[8];
    const float* hm1 = (const float*)d_in[9];
    const float* hv1 = (const float*)d_in[10];
    const float* hw2 = (const float*)d_in[11];
    const float* hg2 = (const float*)d_in[12];
    const float* hb2 = (const float*)d_in[13];
    const float* hm2 = (const float*)d_in[14];
    const float* hv2 = (const float*)d_in[15];
    const float* clsw = (const float*)d_in[16];
    const float* locw = (const float*)d_in[17];
    float* out = (float*)d_out;

    cudaFuncSetAttribute(convmma_k, cudaFuncAttributeMaxDynamicSharedMemorySize,
                         CMM_SMEM);

    wtrans_head_k<<<(256*9*128 + 255)/256, 256>>>(hw1, hg1, hb1, hm1, hv1, 0);
    wtrans_head_k<<<(256*9*128 + 255)/256, 256>>>(hw2, hg2, hb2, hm2, hv2, 1);
    split0_k<<<(TTOT/2 + 255)/256, 256>>>(layer2, layer3, layer4);
    convmma_k<<<336, 256, CMM_SMEM>>>(0);
    split1_k<<<(TTOT/2 + 255)/256, 256>>>();
    convmma_k<<<336, 256, CMM_SMEM>>>(1);

    wtrans_rpn_k<<<(256*9*16 + 255)/256, 256>>>(clsw, locw);
    conv_rpn_k<<<176, 128>>>();

    decode_k<<<(ATOT + 255)/256, 256>>>(anchors2, anchors3, anchors4);
    topk_k<<<6, 1024>>>();
    nms_k<<<6, 256>>>(out);
    roipool_k<<<dim3(32, 2, 3), 256>>>(out);
}

// round 17
// speedup vs baseline: 1.1979x; 1.1535x over previous
#include <cuda_runtime.h>
#include <cuda_bf16.h>
#include <cuda_fp16.h>
#include <math.h>

#define CI 256
#define TOFF0 0
#define TOFF1 2097152
#define TOFF2 2621440
#define TTOT  2752512
#define AOFF0 0
#define AOFF1 24576
#define AOFF2 30720
#define ATOT  32256

__device__ float g_t [TTOT];
__device__ float g_f [TTOT];
__device__ __half2 g_w1h[256*9*128];
__device__ __half2 g_w1l[256*9*128];
__device__ __half2 g_w2h[256*9*128];
__device__ __half2 g_w2l[256*9*128];
__device__ __half2 g_xph[TTOT/2];
__device__ __half2 g_xpl[TTOT/2];
__device__ float g_wtr[256*9*16];
__device__ float g_b1[256];
__device__ float g_b2[256];
__device__ float g_score[ATOT];
__device__ float g_loc [ATOT*4];
__device__ float g_boxes[ATOT*4];
__device__ float g_sval [ATOT];
__device__ unsigned int g_keys[ATOT];
__device__ int   g_topk[6*256];
__device__ int   g_coords[2*3*32*4];
__device__ int   g_mflag [2*3*32];

__device__ __forceinline__ int lvlH(int l) { return (l==0)?64:((l==1)?32:16); }
__device__ __forceinline__ int lvlW(int l) { return (l==0)?64:((l==1)?32:16); }
__device__ __forceinline__ int lvlN(int l) { return (l==0)?12288:((l==1)?3072:768); }
__device__ __forceinline__ size_t lvlTOff(int l){ return (l==0)?TOFF0:((l==1)?(size_t)TOFF1:(size_t)TOFF2); }
__device__ __forceinline__ size_t lvlAOff(int l){ return (l==0)?AOFF0:((l==1)?(size_t)AOFF1:(size_t)AOFF2); }
__device__ __forceinline__ int lvlStride(int l){ return 8 << l; }

__device__ __forceinline__ void cp16(unsigned dst, const void* src) {
    asm volatile("cp.async.ca.shared.global [%0], [%1], 16;" :: "r"(dst), "l"(src));
}
__device__ __forceinline__ void cp16z(unsigned dst, const void* src, int ok) {
    int sz = ok ? 16 : 0;
    asm volatile("cp.async.ca.shared.global [%0], [%1], 16, %2;" :: "r"(dst), "l"(src), "r"(sz));
}
__device__ __forceinline__ void mma_f16(float* c, const unsigned* a, const unsigned* b) {
    asm volatile(
        "mma.sync.aligned.m16n8k16.row.col.f32.f16.f16.f32 "
        "{%0,%1,%2,%3}, {%4,%5,%6,%7}, {%8,%9}, {%0,%1,%2,%3};"
        : "+f"(c[0]), "+f"(c[1]), "+f"(c[2]), "+f"(c[3])
        : "r"(a[0]), "r"(a[1]), "r"(a[2]), "r"(a[3]), "r"(b[0]), "r"(b[1]));
}
#define LDSM4(r, addr) \
    asm volatile("ldmatrix.sync.aligned.m8n8.x4.shared.b16 {%0,%1,%2,%3}, [%4];" \
        : "=r"((r)[0]), "=r"((r)[1]), "=r"((r)[2]), "=r"((r)[3]) : "r"(addr))

// ---- fused weight transform: both head stages + rpn in ONE launch ----
__global__ void wtrans_all_k(const float* __restrict__ hw1, const float* __restrict__ hg1,
                             const float* __restrict__ hb1, const float* __restrict__ hm1,
                             const float* __restrict__ hv1,
                             const float* __restrict__ hw2, const float* __restrict__ hg2,
                             const float* __restrict__ hb2, const float* __restrict__ hm2,
                             const float* __restrict__ hv2,
                             const float* __restrict__ clsw, const float* __restrict__ locw)
{
    int bid = blockIdx.x;
    int tid = threadIdx.x;
    if (bid < 2304) {
        int wsel = bid >= 1152;
        const float* w  = wsel ? hw2 : hw1;
        const float* g  = wsel ? hg2 : hg1;
        const float* bb = wsel ? hb2 : hb1;
        const float* mm = wsel ? hm2 : hm1;
        const float* vv = wsel ? hv2 : hv1;
        __half2* wph = wsel ? g_w2h : g_w1h;
        __half2* wpl = wsel ? g_w2l : g_w1l;
        float* bias = wsel ? g_b2 : g_b1;
        int i = (wsel ? bid - 1152 : bid)*256 + tid;
        if (i < 256) {
            float sc = g[i] / sqrtf(vv[i] + 1e-5f);
            bias[i] = bb[i] - mm[i]*sc;
        }
        if (i >= 256*9*128) return;
        int cp  = i % 128;
        int tap = (i/128) % 9;
        int co  = i / 1152;
        float sc = g[co] / sqrtf(vv[co] + 1e-5f);
        float v0 = w[((size_t)co*256 + 2*cp)*9 + tap] * sc;
        float v1 = w[((size_t)co*256 + 2*cp + 1)*9 + tap] * sc;
        __half h0 = __float2half_rn(v0);
        __half h1 = __float2half_rn(v1);
        wph[i] = __halves2half2(h0, h1);
        wpl[i] = __halves2half2(__float2half_rn(v0 - __half2float(h0)),
                                __float2half_rn(v1 - __half2float(h1)));
    } else {
        int i = (bid - 2304)*256 + tid;
        if (i >= 256*9*16) return;
        int c16 = i % 16;
        int k   = (i/16) % 9;
        int ci  = i / 144;
        float v = 0.f;
        if (c16 < 3)       v = clsw[((size_t)c16*256 + ci)*9 + k];
        else if (c16 < 15) v = locw[((size_t)(c16-3)*256 + ci)*9 + k];
        g_wtr[i] = v;
    }
}

// ---- fused FPN add + f16 hi/lo split + ci-pair pack (stage 0 inputs) ----
__global__ void split0_k(const float* __restrict__ layer2, const float* __restrict__ layer3,
                         const float* __restrict__ layer4)
{
    int gid = blockIdx.x*256 + threadIdx.x;
    if (gid >= TTOT/2) return;
    int l, hwlog, offp;
    if (gid < TOFF1/2)      { l = 0; offp = 0;        hwlog = 12; }
    else if (gid < TOFF2/2) { l = 1; offp = TOFF1/2;  hwlog = 10; }
    else                    { l = 2; offp = TOFF2/2;  hwlog = 8; }
    int HW = 1 << hwlog;
    int local = gid - offp;
    int p = local & (HW - 1);
    int plane = local >> hwlog;
    int img = plane >> 7;
    int cp = plane & 127;
    float v[2];
#pragma unroll
    for (int h = 0; h < 2; h++) {
        int bc = img*256 + 2*cp + h;
        if (l == 0) {
            int y = p >> 6, x = p & 63;
            v[h] = layer2[((size_t)bc << 12) + p]
                 + layer3[((size_t)bc << 10) + ((y>>1)<<5) + (x>>1)]
                 + layer4[((size_t)bc << 8)  + ((y>>2)<<4) + (x>>2)];
        } else if (l == 1) {
            int y = p >> 5, x = p & 31;
            v[h] = layer3[((size_t)bc << 10) + p]
                 + layer4[((size_t)bc << 8)  + ((y>>1)<<4) + (x>>1)];
        } else {
            v[h] = layer4[((size_t)bc << 8) + p];
        }
    }
    __half h0 = __float2half_rn(v[0]);
    __half h1 = __float2half_rn(v[1]);
    __half l0 = __float2half_rn(v[0] - __half2float(h0));
    __half l1 = __float2half_rn(v[1] - __half2float(h1));
    g_xph[gid] = __halves2half2(h0, h1);
    g_xpl[gid] = __halves2half2(l0, l1);
}

__global__ void split1_k()
{
    int gid = blockIdx.x*256 + threadIdx.x;
    if (gid >= TTOT/2) return;
    int l, hwlog, offp;
    if (gid < TOFF1/2)      { l = 0; offp = 0;        hwlog = 12; }
    else if (gid < TOFF2/2) { l = 1; offp = TOFF1/2;  hwlog = 10; }
    else                    { l = 2; offp = TOFF2/2;  hwlog = 8; }
    int HW = 1 << hwlog;
    int local = gid - offp;
    int p = local & (HW - 1);
    int plane = local >> hwlog;
    int img = plane >> 7;
    int cp = plane & 127;
    const float* src = g_t + lvlTOff(l);
    size_t base = ((size_t)(img*256 + 2*cp) << hwlog) + p;
    float v0 = src[base];
    float v1 = src[base + HW];
    __half h0 = __float2half_rn(v0);
    __half h1 = __float2half_rn(v1);
    __half l0 = __float2half_rn(v0 - __half2float(h0));
    __half l1 = __float2half_rn(v1 - __half2float(h1));
    g_xph[gid] = __halves2half2(h0, h1);
    g_xpl[gid] = __halves2half2(l0, l1);
}

// ---- FP16x3 implicit-GEMM conv (R16 config, term-major mma ordering) ----
#define CMM_SMEM 96256
__global__ void __launch_bounds__(256, 2) convmma_k(int stage)
{
    extern __shared__ float sm[];
    const __half2* wph = stage ? g_w2h : g_w1h;
    const __half2* wpl = stage ? g_w2l : g_w1l;
    const float* bias = stage ? g_b2 : g_b1;
    float* outbuf = stage ? g_f : g_t;

    int co0 = (blockIdx.x & 1) << 7;
    int pt = blockIdx.x >> 1;
    int l, img, ptile;
    if (pt < 128)      { l = 0; img = pt >> 6; ptile = pt & 63; }
    else if (pt < 160) { int q = pt - 128; l = 1; img = q >> 4; ptile = q & 15; }
    else               { int q = pt - 160; l = 2; img = q >> 2; ptile = q & 3; }
    int H = lvlH(l), W = lvlW(l);
    int HW = H * W;
    int logW = (l==0)?6:((l==1)?5:4);
    int R  = 64 >> logW;
    int RS = R + 2;
    int RP = W + 8;
    int CPS = (l==0)?216:((l==1)?168:152);
    int BSZ = 16*CPS;
    int Q = W >> 2;
    int logQ = logW - 2;
    int y0 = ptile * R;
    int p0 = ptile * 64;
    size_t toff = lvlTOff(l);
    const __half2* xph = g_xph + (toff>>1) + (size_t)img*128*HW;
    const __half2* xpl = g_xpl + (toff>>1) + (size_t)img*128*HW;

    int tid = threadIdx.x;
    unsigned smb = (unsigned)__cvta_generic_to_shared(sm);

    for (int t = tid; t < 64*RS; t += 256) {
        int r  = t % RS;
        int z  = t / RS;
        int cp = z & 15;
        int pr = (z >> 4) & 1;
        int bf = z >> 5;
        int base = 10240 + bf*2*BSZ + pr*BSZ + cp*CPS + r*RP;
        *(float4*)(sm + base) = make_float4(0.f,0.f,0.f,0.f);
        *(float4*)(sm + base + 4 + W) = make_float4(0.f,0.f,0.f,0.f);
    }

    auto stageB = [&](int sc) {
        unsigned bb = smb + (unsigned)((10240 + (sc & 1)*2*BSZ) * 4);
        int cq0 = sc * 16;
        int items = (RS * Q) << 4;
        for (int t = tid; t < items; t += 256) {
            int q  = t & (Q - 1);
            int rr = t >> logQ;
            int r  = rr % RS;
            int cp = rr / RS;
            int sy = y0 - 1 + r;
            int ok = (sy >= 0) && (sy < H);
            size_t src = (size_t)(cq0 + cp)*HW + (ok ? sy*W : 0) + q*4;
            unsigned d = bb + (unsigned)((cp*CPS + r*RP + 4 + q*4) * 4);
            cp16z(d, xph + src, ok);
            cp16z(d + (unsigned)(BSZ*4), xpl + src, ok);
        }
    };
    auto stageA = [&](int c) {
        int sc = c / 9;
        int tap = c - sc*9;
        unsigned ab = smb + (unsigned)((c & 1)*5120*4);
#pragma unroll
        for (int t = 0; t < 2; t++) {
            int idx = tid + (t << 8);
            int co = idx >> 2, kq = idx & 3;
            unsigned d = ab + (unsigned)((co*20 + kq*4) * 4);
            size_t go = ((size_t)(co0 + co)*9 + tap)*128 + sc*16 + kq*4;
            cp16(d,            wph + go);
            cp16(d + 2560*4,   wpl + go);
        }
    };

    stageB(0);
    stageA(0);
    asm volatile("cp.async.commit_group;" ::: "memory");
    stageA(1);
    asm volatile("cp.async.commit_group;" ::: "memory");

    int lane = tid & 31, wid = tid >> 5;
    int wm = wid & 3, wn = wid >> 2;
    int coL = wm * 32, pxL = wn * 32;
    int lr = lane >> 2, lc = lane & 3;

    unsigned aAddr[2];
#pragma unroll
    for (int m = 0; m < 2; m++)
        aAddr[m] = smb + (unsigned)((((coL + m*16 + (lane & 15))*20) + ((lane >> 4) << 2)) * 4);

    int bOff[4];
#pragma unroll
    for (int n = 0; n < 4; n++) {
        int j = pxL + n*8 + lr;
        bOff[n] = (1 + (j >> logW))*RP + 4 + (j & (W-1));
    }

    float acc[2][4][4];
#pragma unroll
    for (int m = 0; m < 2; m++)
#pragma unroll
        for (int n = 0; n < 4; n++)
#pragma unroll
            for (int q = 0; q < 4; q++) acc[m][n][q] = 0.f;

    for (int c = 0; c < 72; c++) {
        int sc = c / 9;
        int tap = c - sc*9;
        asm volatile("cp.async.wait_group 1;" ::: "memory");
        __syncthreads();
        int dyq = tap / 3;
        int tapOff = (dyq - 1)*RP + (tap - dyq*3 - 1);
        unsigned abuf = (unsigned)((c & 1)*5120*4);
        const float* Bb = sm + 10240 + (sc & 1)*2*BSZ;
#pragma unroll
        for (int st = 0; st < 2; st++) {
            int kb = st * 8;
            unsigned bh[4][2], bl[4][2];
#pragma unroll
            for (int n = 0; n < 4; n++) {
                const float* bp = Bb + (kb + lc)*CPS + bOff[n] + tapOff;
                bh[n][0] = *(const unsigned*)(bp);
                bh[n][1] = *(const unsigned*)(bp + 4*CPS);
                bl[n][0] = *(const unsigned*)(bp + BSZ);
                bl[n][1] = *(const unsigned*)(bp + 4*CPS + BSZ);
            }
            unsigned ah[2][4], al[2][4];
#pragma unroll
            for (int m = 0; m < 2; m++) {
                unsigned base = aAddr[m] + abuf + (unsigned)(kb * 4);
                LDSM4(ah[m], base);
                LDSM4(al[m], base + 2560*4);
            }
#pragma unroll
            for (int m = 0; m < 2; m++)
#pragma unroll
                for (int n = 0; n < 4; n++)
                    mma_f16(acc[m][n], ah[m], bh[n]);
#pragma unroll
            for (int m = 0; m < 2; m++)
#pragma unroll
                for (int n = 0; n < 4; n++)
                    mma_f16(acc[m][n], ah[m], bl[n]);
#pragma unroll
            for (int m = 0; m < 2; m++)
#pragma unroll
                for (int n = 0; n < 4; n++)
                    mma_f16(acc[m][n], al[m], bh[n]);
        }
        __syncthreads();
        if (c + 2 < 72) stageA(c + 2);
        if (tap == 5 && sc < 7) stageB(sc + 1);
        asm volatile("cp.async.commit_group;" ::: "memory");
    }

    float* outp = outbuf + toff + (size_t)img*256*HW;
#pragma unroll
    for (int m = 0; m < 2; m++) {
        int co = co0 + coL + m*16 + lr;
        float b0 = bias[co], b1 = bias[co + 8];
#pragma unroll
        for (int n = 0; n < 4; n++) {
            int pxo = p0 + pxL + n*8 + lc*2;
            float t0 = acc[m][n][0] + b0;
            float t1 = acc[m][n][1] + b0;
            float t2 = acc[m][n][2] + b1;
            float t3 = acc[m][n][3] + b1;
            t0 = (t0 >= 0.f) ? t0 : 0.01f*t0;
            t1 = (t1 >= 0.f) ? t1 : 0.01f*t1;
            t2 = (t2 >= 0.f) ? t2 : 0.01f*t2;
            t3 = (t3 >= 0.f) ? t3 : 0.01f*t3;
            *(float2*)(outp + (size_t)co*HW + pxo)     = make_float2(t0, t1);
            *(float2*)(outp + (size_t)(co+8)*HW + pxo) = make_float2(t2, t3);
        }
    }
}

// ---- RPN conv (FFMA, 32x2 px, 16 co, 176 blocks) ----
#define CI_C 16
#define RISTR 40
__global__ __launch_bounds__(128, 4)
void conv_rpn_k()
{
    __shared__ float s_in[CI_C*4*RISTR];
    __shared__ float s_w [CI_C*9*16];

    int bid = blockIdx.x;
    int l, bx, by, img;
    if (bid < 128)      { l = 0; bx = bid & 1; by = (bid >> 1) & 31; img = bid >> 6; }
    else if (bid < 160) { int q = bid - 128; l = 1; bx = 0; by = q & 15; img = q >> 4; }
    else                { int q = bid - 160; l = 2; bx = 0; by = q & 7;  img = q >> 3; }
    int H = lvlH(l), W = lvlW(l);
    int HW = H * W;
    int tx = bx * 32;
    int ty = by * 2;

    int tid = threadIdx.x;
    int px  = tid & 7;
    int py  = (tid >> 3) & 1;
    int cog = tid >> 4;

    const float* inb = g_f + lvlTOff(l) + (size_t)img*256*HW;

    float acc[2][4];
#pragma unroll
    for (int a = 0; a < 2; a++)
#pragma unroll
        for (int m = 0; m < 4; m++) acc[a][m] = 0.f;

    for (int ci0 = 0; ci0 < CI; ci0 += CI_C) {
        if (ci0) __syncthreads();
        for (int i = tid; i < CI_C*4*34; i += 128) {
            int cc = i / 136;
            int r  = i % 136;
            int yy = r / 34;
            int xx = r % 34;
            int gy = ty + yy - 1;
            int gx = tx + xx - 1;
            float v = 0.f;
            if (gy >= 0 && gy < H && gx >= 0 && gx < W)
                v = inb[((size_t)(ci0+cc))*HW + gy*W + gx];
            s_in[(cc*4 + yy)*RISTR + xx] = v;
        }
        for (int i = tid; i < CI_C*9*16; i += 128) {
            int cc = i / 144;
            int r  = i % 144;
            s_w[i] = g_wtr[((size_t)(ci0+cc))*144 + r];
        }
        __syncthreads();

#pragma unroll 1
        for (int cc = 0; cc < CI_C; cc++) {
#pragma unroll
            for (int ky = 0; ky < 3; ky++) {
                const float* rowp = &s_in[(cc*4 + py + ky)*RISTR];
#pragma unroll
                for (int kx = 0; kx < 3; kx++) {
                    float2 w2 = *(const float2*)&s_w[(cc*9 + ky*3 + kx)*16 + cog*2];
#pragma unroll
                    for (int m = 0; m < 4; m++) {
                        float v = rowp[px + 8*m + kx];
                        acc[0][m] += v * w2.x;
                        acc[1][m] += v * w2.y;
                    }
                }
            }
        }
    }

    int y = ty + py;
    size_t abase = lvlAOff(l) + (size_t)img*lvlN(l);
#pragma unroll
    for (int m = 0; m < 4; m++) {
        int x = tx + px + 8*m;
        if (x >= W) continue;
#pragma unroll
        for (int a = 0; a < 2; a++) {
            int co = cog*2 + a;
            if (co >= 15) break;
            float vv = acc[a][m];
            if (co < 3) {
                g_score[abase + ((size_t)y*W + x)*3 + co] = 1.f/(1.f + expf(-vv));
            } else {
                int cr = co - 3;
                g_loc[(abase + ((size_t)y*W + x)*3 + (cr>>2))*4 + (cr&3)] = vv;
            }
        }
    }
}

// ---- decode ----
__global__ void decode_k(const float* __restrict__ anch0, const float* __restrict__ anch1,
                         const float* __restrict__ anch2)
{
    int gid = blockIdx.x*256 + threadIdx.x;
    if (gid >= ATOT) return;
    int l, r;
    const float* anchors;
    if (gid < AOFF1)      { l = 0; r = gid;         anchors = anch0; }
    else if (gid < AOFF2) { l = 1; r = gid - AOFF1; anchors = anch1; }
    else                  { l = 2; r = gid - AOFF2; anchors = anch2; }
    int N = lvlN(l);
    int a = r % N;
    float stride = (float)lvlStride(l);

    float sc = g_score[gid];
    float t0 = g_loc[(size_t)gid*4 + 0];
    float t1 = g_loc[(size_t)gid*4 + 1];
    float t2 = g_loc[(size_t)gid*4 + 2];
    float t3 = g_loc[(size_t)gid*4 + 3];
    float a0 = anchors[(size_t)a*4+0], a1 = anchors[(size_t)a*4+1];
    float a2 = anchors[(size_t)a*4+2], a3 = anchors[(size_t)a*4+3];
    float aw = a2 - a0, ah = a3 - a1;
    float x1 = a0 + t0*aw;
    float y1 = a1 + t1*ah;
    float x2 = x1 + aw*expf(t2);
    float y2 = y1 + ah*expf(t3);
    x1 = fminf(fmaxf(x1, 0.f), 512.f);
    y1 = fminf(fmaxf(y1, 0.f), 512.f);
    x2 = fminf(fmaxf(x2, 0.f), 512.f);
    y2 = fminf(fmaxf(y2, 0.f), 512.f);
    bool valid = (sc > 0.5f) && ((x2 - x1) >= 2.f*stride) && ((y2 - y1) >= 2.f*stride);
    float s = valid ? sc : -1.f;
    size_t o = (size_t)gid*4;
    g_boxes[o+0] = x1; g_boxes[o+1] = y1; g_boxes[o+2] = x2; g_boxes[o+3] = y2;
    g_sval[gid] = s;
    unsigned int u = __float_as_uint(s);
    u = (u & 0x80000000u) ? ~u : (u | 0x80000000u);
    g_keys[gid] = u;
}

// ---- exact top-256 via MSB radix select ----
__global__ void topk_k()
{
    __shared__ unsigned int hist[256];
    __shared__ unsigned long long lst[256];
    __shared__ unsigned int wsum[32];
    __shared__ unsigned int sPrefix;
    __shared__ int sK, sCGT, sCnt, sTot, sDone;

    int blk = blockIdx.x;
    int l = blk >> 1;
    int b = blk & 1;
    int N = lvlN(l);
    const unsigned int* keys = g_keys + lvlAOff(l) + (size_t)b*N;
    int tid = threadIdx.x;

    if (tid == 0) { sPrefix = 0u; sK = 256; sCGT = 0; sCnt = 0; sDone = 0; }
    __syncthreads();

    for (int byte = 3; byte >= 0; byte--) {
        for (int i = tid; i < 256; i += 1024) hist[i] = 0u;
        __syncthreads();
        unsigned int pf = sPrefix;
        unsigned int mask = (byte == 3) ? 0u : (0xFFFFFFFFu << ((byte+1)*8));
        for (int i = tid; i < N; i += 1024) {
            unsigned int k = keys[i];
            if ((k & mask) == pf) atomicAdd(&hist[(k >> (byte*8)) & 255], 1u);
        }
        __syncthreads();
        if (tid == 0) {
            int cum = 0;
            int kk = sK;
            int v = 255;
            for (; v >= 0; v--) {
                int c = (int)hist[v];
                if (cum + c >= kk) break;
                cum += c;
            }
            sPrefix |= ((unsigned int)v) << (byte*8);
            sK = kk - cum;
            sCGT += cum;
        }
        __syncthreads();
    }

    unsigned int T = sPrefix;
    int need = sK;
    int cg = sCGT;

    for (int i = tid; i < N; i += 1024) {
        unsigned int k = keys[i];
        if (k > T) {
            int p = atomicAdd(&sCnt, 1);
            lst[p] = ((unsigned long long)k << 32) | (unsigned int)(0xFFFFFFFFu - i);
        }
    }
    __syncthreads();
    if (tid < 256 && tid >= cg) lst[tid] = 0ull;
    __syncthreads();

    for (int k = 2; k <= 256; k <<= 1) {
        for (int j = k >> 1; j > 0; j >>= 1) {
            if (tid < 256) {
                int ixj = tid ^ j;
                if (ixj > tid) {
                    bool desc = ((tid & k) == 0);
                    unsigned long long A = lst[tid], Bv = lst[ixj];
                    bool sw = desc ? (A < Bv) : (A > Bv);
                    if (sw) { lst[tid] = Bv; lst[ixj] = A; }
                }
            }
            __syncthreads();
        }
    }

    if (tid < cg)
        g_topk[blk*256 + tid] = (int)(0xFFFFFFFFu - (unsigned int)(lst[tid] & 0xFFFFFFFFull));

    for (int base = 0; base < N; base += 1024) {
        __syncthreads();
        if (sDone >= need) break;
        int i = base + tid;
        int flag = (i < N) && (keys[i] == T);
        unsigned int m = __ballot_sync(0xffffffffu, flag);
        int lane = tid & 31, wd = tid >> 5;
        int laneoff = __popc(m & ((1u << lane) - 1u));
        if (lane == 0) wsum[wd] = __popc(m);
        __syncthreads();
        if (tid == 0) {
            int run = 0;
            for (int w = 0; w < 32; w++) { int c = (int)wsum[w]; wsum[w] = run; run += c; }
            sTot = run;
        }
        __syncthreads();
        if (flag) {
            int pos = sDone + (int)wsum[wd] + laneoff;
            if (pos < need) g_topk[blk*256 + cg + pos] = i;
        }
        __syncthreads();
        if (tid == 0) sDone += sTot;
    }
}

// ---- greedy NMS ----
__global__ void nms_k(float* __restrict__ dout)
{
    __shared__ float bxs[256][4];
    __shared__ float varea[256];
    __shared__ float vvs[256];
    __shared__ int keep[256];
    __shared__ int ord[32];
    int blk = blockIdx.x;
    int lvl = blk >> 1;
    int b = blk & 1;
    int N = lvlN(lvl);
    int stride = lvlStride(lvl);
    size_t abase = lvlAOff(lvl) + (size_t)b*N;
    int j = threadIdx.x;
    int idx = g_topk[blk*256 + j];
    float x1 = g_boxes[(abase + idx)*4 + 0];
    float y1 = g_boxes[(abase + idx)*4 + 1];
    float x2 = g_boxes[(abase + idx)*4 + 2];
    float y2 = g_boxes[(abase + idx)*4 + 3];
    float v  = g_sval[abase + idx];
    bxs[j][0] = x1; bxs[j][1] = y1; bxs[j][2] = x2; bxs[j][3] = y2;
    vvs[j] = v;
    float areaj = (x2 - x1 + 1.f)*(y2 - y1 + 1.f);
    varea[j] = areaj;
    keep[j] = (v > 0.5f) ? 1 : 0;
    __syncthreads();
    for (int i = 0; i < 255; i++) {
        if (j > i && keep[i] && keep[j]) {
            float xx1 = fmaxf(bxs[i][0], x1);
            float yy1 = fmaxf(bxs[i][1], y1);
            float xx2 = fminf(bxs[i][2], x2);
            float yy2 = fminf(bxs[i][3], y2);
            float iw = fmaxf(0.f, xx2 - xx1 + 1.f);
            float ih = fmaxf(0.f, yy2 - yy1 + 1.f);
            float inter = iw*ih;
            float iou = inter / (varea[i] + areaj - inter);
            if (iou > 0.3f) keep[j] = 0;
        }
        __syncthreads();
    }
    if (j == 0) {
        int c = 0;
        for (int q = 0; q < 256 && c < 32; q++) if (keep[q]) ord[c++] = q;
        for (int q = 0; q < 256 && c < 32; q++) if (!keep[q]) ord[c++] = q;
    }
    __syncthreads();
    if (j < 32) {
        int o = ord[j];
        int m = keep[o];
        int slot = (b*3 + lvl)*32 + j;
        size_t dbase = (size_t)slot*5;
        if (m) {
            dout[dbase+0] = bxs[o][0];
            dout[dbase+1] = bxs[o][1];
            dout[dbase+2] = bxs[o][2];
            dout[dbase+3] = bxs[o][3];
            dout[dbase+4] = vvs[o];
        } else {
            dout[dbase+0] = 0.f; dout[dbase+1] = 0.f; dout[dbase+2] = 0.f;
            dout[dbase+3] = 0.f; dout[dbase+4] = 0.f;
        }
        dout[960 + slot] = m ? 1.f : 0.f;
        if (m) {
            g_coords[slot*4+0] = ((int)bxs[o][0]) / stride;
            g_coords[slot*4+1] = ((int)bxs[o][1]) / stride;
            g_coords[slot*4+2] = ((int)bxs[o][2]) / stride;
            g_coords[slot*4+3] = ((int)bxs[o][3]) / stride;
        } else {
            g_coords[slot*4+0] = 0; g_coords[slot*4+1] = 0;
            g_coords[slot*4+2] = 2; g_coords[slot*4+3] = 2;
        }
        g_mflag[slot] = m;
    }
}

// ---- ROI adaptive 7x7 max pool: one block per (slot, ybin-row) ----
// grid (32, 2, 21): z = lvl*7 + i ; per-thread loads drop ~7x.
__global__ void roipool_k(float* __restrict__ dout)
{
    int s = blockIdx.x;
    int b = blockIdx.y;
    int z = blockIdx.z;
    int lvl = z / 7;
    int i = z - lvl*7;
    int c = threadIdx.x;
    int H = lvlH(lvl), W = lvlW(lvl);
    int slot = (b*3 + lvl)*32 + s;
    float* dst = dout + 1152 + ((size_t)slot*256 + c)*49;
    int m = g_mflag[slot];
    if (!m) {
#pragma unroll
        for (int jx = 0; jx < 7; jx++) dst[i*7 + jx] = 0.f;
        return;
    }
    int x1 = g_coords[slot*4+0];
    int y1 = g_coords[slot*4+1];
    int x2 = g_coords[slot*4+2];
    int y2 = g_coords[slot*4+3];
    int Lx = x2 - x1;
    int Ly = y2 - y1;
    const float* f = g_f + lvlTOff(lvl) + ((size_t)b*256 + c)*H*W;
    int ys = y1 + (i*Ly)/7;
    int ye = y1 + ((i+1)*Ly + 6)/7;
    for (int jx = 0; jx < 7; jx++) {
        int xs = x1 + (jx*Lx)/7;
        int xe = x1 + ((jx+1)*Lx + 6)/7;
        float mx = -3.402823466e38f;
        for (int y = ys; y < ye; y++)
            for (int x = xs; x < xe; x++)
                mx = fmaxf(mx, f[y*W + x]);
        dst[i*7 + jx] = mx;
    }
}

// ---- host orchestration (kernel launches ONLY) ----
extern "C" void kernel_launch(void* const* d_in, const int* in_sizes, int n_in,
                              void* d_out, int out_size)
{
    const float* layer2   = (const float*)d_in[0];
    const float* layer3   = (const float*)d_in[1];
    const float* layer4   = (const float*)d_in[2];
    const float* anchors2 = (const float*)d_in[3];
    const float* anchors3 = (const float*)d_in[4];
    const float* anchors4 = (const float*)d_in[5];
    const float* hw1 = (const float*)d_in[6];
    const float* hg1 = (const float*)d_in[7];
    const float* hb1 = (const float*)d_in[8];
    const float* hm1 = (const float*)d_in[9];
    const float* hv1 = (const float*)d_in[10];
    const float* hw2 = (const float*)d_in[11];
    const float* hg2 = (const float*)d_in[12];
    const float* hb2 = (const float*)d_in[13];
    const float* hm2 = (const float*)d_in[14];
    const float* hv2 = (const float*)d_in[15];
    const float* clsw = (const float*)d_in[16];
    const float* locw = (const float*)d_in[17];
    float* out = (float*)d_out;

    cudaFuncSetAttribute(convmma_k, cudaFuncAttributeMaxDynamicSharedMemorySize,
                         CMM_SMEM);

    wtrans_all_k<<<2448, 256>>>(hw1, hg1, hb1, hm1, hv1,
                                hw2, hg2, hb2, hm2, hv2, clsw, locw);
    split0_k<<<(TTOT/2 + 255)/256, 256>>>(layer2, layer3, layer4);
    convmma_k<<<336, 256, CMM_SMEM>>>(0);
    split1_k<<<(TTOT/2 + 255)/256, 256>>>();
    convmma_k<<<336, 256, CMM_SMEM>>>(1);

    conv_rpn_k<<<176, 128>>>();

    decode_k<<<(ATOT + 255)/256, 256>>>(anchors2, anchors3, anchors4);
    topk_k<<<6, 1024>>>();
    nms_k<<<6, 256>>>(out);
    roipool_k<<<dim3(32, 2, 21), 256>>>(out);
}